// round 7
// baseline (speedup 1.0000x reference)
#include <cuda_runtime.h>
#include <math.h>

#define B_    32
#define L_    64
#define D_    768
#define LL_   (L_*L_)     // 4096
#define OUTD_ (2*D_)      // 1536
#define GRID_ 148
#define NT_   512
#define NW_   16          // warps per block

#define KSL_  6           // K slices for GEMM (768/128)
#define KCH_  128         // k per slice
#define OCH_  32          // outputs per task
#define NTASK_ (KSL_ * (OUTD_/OCH_))   // 288 GEMM tasks

// scratch (zero-init at load; barrier counters monotonic -> replay-safe)
__device__ float    g_pooled[B_ * D_];
__device__ float    g_t[B_ * 2 * L_];
__device__ float    g_ca[B_ * L_];
__device__ float    g_cb[B_ * L_];
__device__ float    g_part[KSL_ * B_ * OUTD_];   // 1.2 MB, L2-resident
__device__ unsigned g_bar[8];

__device__ __forceinline__ void gsync(int i)
{
    __threadfence();
    __syncthreads();
    if (threadIdx.x == 0) {
        unsigned v = atomicAdd(&g_bar[i], 1u) + 1u;
        unsigned target = ((v - 1u) / GRID_ + 1u) * GRID_;
        while (*((volatile unsigned*)&g_bar[i]) < target) __nanosleep(32);
    }
    __syncthreads();
    __threadfence();
}

__global__ __launch_bounds__(NT_, 1) void fused(
    const float* __restrict__ a1, const float* __restrict__ a2,
    const int*   __restrict__ m1, const int*   __restrict__ m2,
    const float* __restrict__ we_w,
    const float* __restrict__ fc_w, const float* __restrict__ fc_b,
    float* __restrict__ out)
{
    __shared__ float  sw[D_];             // 3 KB  (T)
    __shared__ float  t1[L_], t2[L_];     //       (M)
    __shared__ float  rowsh[L_], colsh[L_];
    __shared__ float  red[NW_];
    __shared__ int    sl1, sl2;
    __shared__ float  smax, sinvd;
    __shared__ float4 partt[NW_][32];     // 8 KB  (A2)
    __shared__ float4 w_s[OCH_ * (KCH_/4)];   // 16 KB (B1) [o_loc*32 + kq]
    __shared__ float4 p_s[(KCH_/4) * B_];     // 16 KB (B1) [kq*32 + b]

    const int tid  = threadIdx.x;
    const int lane = tid & 31;
    const int wid  = tid >> 5;
    const int bid  = blockIdx.x;

    // ============================ Phase T ===============================
    for (int i = tid; i < D_; i += NT_) sw[i] = we_w[i];
    __syncthreads();

    const float4* swv = (const float4*)sw;
    for (int wt = bid * NW_ + wid; wt < B_ * 2 * L_; wt += GRID_ * NW_) {
        const int b    = wt >> 7;
        const int task = wt & 127;
        const float4* row = (task < L_)
            ? ((const float4*)(a1 + (size_t)b * L_ * D_) + task * (D_/4))
            : ((const float4*)(a2 + (size_t)b * L_ * D_) + (task - L_) * (D_/4));
        float s = 0.f;
        #pragma unroll
        for (int k = 0; k < 6; k++) {
            float4 v = row[lane + 32*k];
            float4 w = swv[lane + 32*k];
            s += v.x*w.x + v.y*w.y + v.z*w.z + v.w*w.w;
        }
        #pragma unroll
        for (int o = 16; o; o >>= 1) s += __shfl_xor_sync(0xffffffffu, s, o);
        if (lane == 0) g_t[b * 2*L_ + task] = s;
    }
    gsync(0);

    // ===================== Phase M (blocks 0..31) =======================
    // other blocks prefetch fc_w into L2 meanwhile
    if (bid < B_) {
        const int b = bid;
        if (tid < 2*L_) {
            float v = g_t[b*2*L_ + tid];
            if (tid < L_) t1[tid] = v; else t2[tid - L_] = v;
        }
        if (tid < L_) { rowsh[tid] = 0.f; colsh[tid] = 0.f; }

        if (wid == 0) {
            int s = m1[b*L_ + lane] + m1[b*L_ + lane + 32];
            #pragma unroll
            for (int o = 16; o; o >>= 1) s += __shfl_xor_sync(0xffffffffu, s, o);
            if (lane == 0) sl1 = s - 2;
        } else if (wid == 1) {
            int s = m2[b*L_ + lane] + m2[b*L_ + lane + 32];
            #pragma unroll
            for (int o = 16; o; o >>= 1) s += __shfl_xor_sync(0xffffffffu, s, o);
            if (lane == 0) sl2 = s - 2;
        }
        __syncthreads();

        const int l1 = sl1, l2 = sl2;

        float lmax = -1e7f;
        for (int i = wid; i < l1; i += NW_) {
            const float ti = t1[i+1];
            #pragma unroll
            for (int base = 0; base < L_; base += 32) {
                int j = base + lane;
                if (j < l2) {
                    float we = ti - t2[j+1];
                    float m = (fabsf(we) < 1e-7f) ? -1e7f : we;
                    lmax = fmaxf(lmax, m);
                }
            }
        }
        #pragma unroll
        for (int o = 16; o; o >>= 1) lmax = fmaxf(lmax, __shfl_xor_sync(0xffffffffu, lmax, o));
        if (lane == 0) red[wid] = lmax;
        __syncthreads();
        if (tid == 0) {
            float m = red[0];
            #pragma unroll
            for (int i = 1; i < NW_; i++) m = fmaxf(m, red[i]);
            smax = m;
        }
        __syncthreads();
        const float mx = smax;

        for (int i = wid; i < l1; i += NW_) {
            const float ti = t1[i+1];
            float s = 0.f;
            #pragma unroll
            for (int base = 0; base < L_; base += 32) {
                int j = base + lane;
                if (j < l2) {
                    float we = ti - t2[j+1];
                    float m = (fabsf(we) < 1e-7f) ? -1e7f : we;
                    s += __expf(m - mx);
                }
            }
            #pragma unroll
            for (int o = 16; o; o >>= 1) s += __shfl_xor_sync(0xffffffffu, s, o);
            if (lane == 0) rowsh[i] = s;
        }
        for (int j = wid; j < l2; j += NW_) {
            const float tj = t2[j+1];
            float s = 0.f;
            #pragma unroll
            for (int base = 0; base < L_; base += 32) {
                int i = base + lane;
                if (i < l1) {
                    float we = t1[i+1] - tj;
                    float m = (fabsf(we) < 1e-7f) ? -1e7f : we;
                    s += __expf(m - mx);
                }
            }
            #pragma unroll
            for (int o = 16; o; o >>= 1) s += __shfl_xor_sync(0xffffffffu, s, o);
            if (lane == 0) colsh[j] = s;
        }
        __syncthreads();

        if (wid == 0) {
            float s = rowsh[lane] + rowsh[lane + 32];
            #pragma unroll
            for (int o = 16; o; o >>= 1) s += __shfl_xor_sync(0xffffffffu, s, o);
            if (lane == 0) {
                float pad = (float)(LL_ - l1*l2) * __expf(-1e7f - mx);
                sinvd = 1.f / (s + pad);
            }
        }
        __syncthreads();
        const float invd = sinvd;

        if (tid < L_) {
            g_ca[bid*L_ + tid] = (tid >= 1 && tid - 1 < l1) ? rowsh[tid-1] * invd : 0.f;
        } else if (tid < 2*L_) {
            int j = tid - L_;
            g_cb[bid*L_ + j] = (j >= 1 && j - 1 < l2) ? -colsh[j-1] * invd : 0.f;
        }
    } else {
        // prefetch fc_w (4.7MB = 36864 x 128B lines) into L2
        int idx = (bid - B_) * NT_ + tid;                 // 0 .. 59391
        const int nlines = OUTD_ * D_ * 4 / 128;          // 36864
        if (idx < nlines) {
            const char* p = (const char*)fc_w + (size_t)idx * 128;
            asm volatile("prefetch.global.L2 [%0];" :: "l"(p));
        }
    }
    gsync(1);

    // ============================ Phase A2 ==============================
    for (int t = bid; t < 6 * B_; t += GRID_) {
        const int b   = t / 6;
        const int cc  = t % 6;
        const int col = cc*32 + lane;

        const float4* base1v = (const float4*)(a1 + (size_t)b * L_ * D_);
        const float4* base2v = (const float4*)(a2 + (size_t)b * L_ * D_);
        const float*  ca = g_ca + b*L_;
        const float*  cb = g_cb + b*L_;

        float4 acc = make_float4(0.f, 0.f, 0.f, 0.f);
        #pragma unroll
        for (int k = 0; k < 4; k++) {
            const int r = wid + NW_*k;
            const float c1 = ca[r];
            const float c2 = cb[r];
            float4 v1 = base1v[r*(D_/4) + col];
            float4 v2 = base2v[r*(D_/4) + col];
            acc.x += c1*v1.x + c2*v2.x;
            acc.y += c1*v1.y + c2*v2.y;
            acc.z += c1*v1.z + c2*v2.z;
            acc.w += c1*v1.w + c2*v2.w;
        }
        partt[wid][lane] = acc;
        __syncthreads();
        if (tid < 32) {
            float4 s = partt[0][lane];
            #pragma unroll
            for (int k = 1; k < NW_; k++) {
                float4 v = partt[k][lane];
                s.x += v.x; s.y += v.y; s.z += v.z; s.w += v.w;
            }
            ((float4*)g_pooled)[b*(D_/4) + col] = s;
        }
        __syncthreads();
    }
    gsync(2);

    // ===================== Phase B1: GEMM partials ======================
    // task = (o-chunk of 32, k-slice of 128). 288 tasks.
    // thread: b = lane-mapped batch, 2 outputs, k-loop in float4 quads.
    {
        const float4* fw4   = (const float4*)fc_w;
        const float4* pool4 = (const float4*)g_pooled;
        const int b    = tid & 31;
        const int ogrp = tid >> 5;          // 0..15 -> outputs ogrp*2, ogrp*2+1

        for (int tt = bid; tt < NTASK_; tt += GRID_) {
            const int ks = tt % KSL_;
            const int oc = tt / KSL_;
            const int o0 = oc * OCH_;
            const int k4 = ks * (KCH_/4);   // float4 k offset

            // stage w: 32 o x 32 kq = 1024 float4 (2/thread, coalesced per row)
            #pragma unroll
            for (int r = 0; r < 2; r++) {
                int idx   = tid + NT_*r;
                int o_loc = idx >> 5;
                int kq    = idx & 31;
                w_s[o_loc*32 + kq] = fw4[(size_t)(o0 + o_loc)*(D_/4) + k4 + kq];
            }
            // stage p: 32 kq x 32 b = 1024 float4 (2/thread)
            #pragma unroll
            for (int r = 0; r < 2; r++) {
                int idx = tid + NT_*r;
                int kq  = idx >> 5;
                int bb  = idx & 31;
                p_s[kq*32 + bb] = pool4[bb*(D_/4) + k4 + kq];
            }
            __syncthreads();

            float acc0 = 0.f, acc1 = 0.f;
            const float4* wr0 = &w_s[(ogrp*2 + 0)*32];
            const float4* wr1 = &w_s[(ogrp*2 + 1)*32];
            #pragma unroll 8
            for (int kq = 0; kq < 32; kq++) {
                float4 pq = p_s[kq*32 + b];
                float4 w0 = wr0[kq];
                float4 w1 = wr1[kq];
                acc0 += pq.x*w0.x + pq.y*w0.y + pq.z*w0.z + pq.w*w0.w;
                acc1 += pq.x*w1.x + pq.y*w1.y + pq.z*w1.z + pq.w*w1.w;
            }
            const int obase = o0 + ogrp*2;
            g_part[(size_t)(ks*B_ + b)*OUTD_ + obase + 0] = acc0;
            g_part[(size_t)(ks*B_ + b)*OUTD_ + obase + 1] = acc1;
            __syncthreads();
        }
    }
    gsync(3);

    // ===================== Phase B2: reduce + tanh ======================
    {
        const float4* part4 = (const float4*)g_part;
        for (int idx = bid * NT_ + tid; idx < B_ * (OUTD_/4); idx += GRID_ * NT_) {
            const int b  = idx / (OUTD_/4);
            const int o4 = idx % (OUTD_/4);
            float4 s = make_float4(0.f, 0.f, 0.f, 0.f);
            #pragma unroll
            for (int ks = 0; ks < KSL_; ks++) {
                float4 v = part4[(size_t)(ks*B_ + b)*(OUTD_/4) + o4];
                s.x += v.x; s.y += v.y; s.z += v.z; s.w += v.w;
            }
            float4 bias = ((const float4*)fc_b)[o4];
            float4 r;
            r.x = tanhf(s.x + bias.x);
            r.y = tanhf(s.y + bias.y);
            r.z = tanhf(s.z + bias.z);
            r.w = tanhf(s.w + bias.w);
            ((float4*)out)[(size_t)b*(OUTD_/4) + o4] = r;
        }
    }
}

extern "C" void kernel_launch(void* const* d_in, const int* in_sizes, int n_in,
                              void* d_out, int out_size)
{
    const float* a1   = (const float*)d_in[0];
    const float* a2   = (const float*)d_in[1];
    const int*   m1   = (const int*)  d_in[2];
    const int*   m2   = (const int*)  d_in[3];
    const float* we_w = (const float*)d_in[4];
    const float* fc_w = (const float*)d_in[5];
    const float* fc_b = (const float*)d_in[6];
    float* out = (float*)d_out;

    fused<<<GRID_, NT_>>>(a1, a2, m1, m2, we_w, fc_w, fc_b, out);
}

// round 8
// speedup vs baseline: 1.1568x; 1.1568x over previous
#include <cuda_runtime.h>
#include <math.h>

#define B_    32
#define L_    64
#define D_    768
#define LL_   (L_*L_)     // 4096
#define OUTD_ (2*D_)      // 1536

// scratch
__device__ float g_pooled[B_ * D_];
__device__ float g_t[B_ * 2 * L_];   // t1 (64) then t2 (64) per batch

// ---------------------------------------------------------------------------
// T: t[b, r] = dot(row, we_w). grid = (16, B_) = 512 blocks, warp per row.
// ---------------------------------------------------------------------------
__global__ __launch_bounds__(256) void stageT(
    const float* __restrict__ a1, const float* __restrict__ a2,
    const float* __restrict__ we_w)
{
    __shared__ float sw[D_];
    const int b    = blockIdx.y;
    const int lane = threadIdx.x & 31;
    const int wid  = threadIdx.x >> 5;
    const int task = blockIdx.x * 8 + wid;   // 0..127

    for (int i = threadIdx.x; i < D_; i += 256) sw[i] = we_w[i];
    __syncthreads();

    const float4* row = (task < L_)
        ? ((const float4*)(a1 + (size_t)b * L_ * D_) + task * (D_/4))
        : ((const float4*)(a2 + (size_t)b * L_ * D_) + (task - L_) * (D_/4));
    const float4* swv = (const float4*)sw;

    float s = 0.f;
    #pragma unroll
    for (int k = 0; k < 6; k++) {
        float4 v = row[lane + 32*k];
        float4 w = swv[lane + 32*k];
        s += v.x*w.x + v.y*w.y + v.z*w.z + v.w*w.w;
    }
    #pragma unroll
    for (int o = 16; o; o >>= 1) s += __shfl_xor_sync(0xffffffffu, s, o);
    if (lane == 0) g_t[b * 2*L_ + task] = s;
}

// ---------------------------------------------------------------------------
// MA2: merged marginals (recomputed redundantly per block) + pooled chunk.
// grid = (6, B_) = 192 blocks, 256 threads. Block handles batch b = blockIdx.y,
// float4 columns [cc*32, cc*32+32).
// ---------------------------------------------------------------------------
__global__ __launch_bounds__(256) void stageMA2(
    const float* __restrict__ a1, const float* __restrict__ a2,
    const int*   __restrict__ m1, const int*   __restrict__ m2)
{
    __shared__ float  t1[L_], t2[L_];
    __shared__ float  rowsh[L_], colsh[L_];
    __shared__ float  ca[L_], cb[L_];
    __shared__ float  red[8];
    __shared__ int    sl1, sl2;
    __shared__ float  smax, sinvd;
    __shared__ float4 partt[8][32];

    const int b    = blockIdx.y;
    const int cc   = blockIdx.x;
    const int tid  = threadIdx.x;
    const int lane = tid & 31;
    const int wid  = tid >> 5;

    // ---- load t values ----
    if (tid < 2*L_) {
        float v = g_t[b*2*L_ + tid];
        if (tid < L_) t1[tid] = v; else t2[tid - L_] = v;
    }
    if (tid < L_) { rowsh[tid] = 0.f; colsh[tid] = 0.f; }

    if (wid == 0) {
        int s = m1[b*L_ + lane] + m1[b*L_ + lane + 32];
        #pragma unroll
        for (int o = 16; o; o >>= 1) s += __shfl_xor_sync(0xffffffffu, s, o);
        if (lane == 0) sl1 = s - 2;
    } else if (wid == 1) {
        int s = m2[b*L_ + lane] + m2[b*L_ + lane + 32];
        #pragma unroll
        for (int o = 16; o; o >>= 1) s += __shfl_xor_sync(0xffffffffu, s, o);
        if (lane == 0) sl2 = s - 2;
    }
    __syncthreads();

    const int l1 = sl1, l2 = sl2;

    // ---- max over valid masked logits (padding floor -1e7) ----
    float lmax = -1e7f;
    for (int i = wid; i < l1; i += 8) {
        const float ti = t1[i+1];
        #pragma unroll
        for (int base = 0; base < L_; base += 32) {
            int j = base + lane;
            if (j < l2) {
                float we = ti - t2[j+1];
                float m = (fabsf(we) < 1e-7f) ? -1e7f : we;
                lmax = fmaxf(lmax, m);
            }
        }
    }
    #pragma unroll
    for (int o = 16; o; o >>= 1) lmax = fmaxf(lmax, __shfl_xor_sync(0xffffffffu, lmax, o));
    if (lane == 0) red[wid] = lmax;
    __syncthreads();
    if (tid == 0) {
        float m = red[0];
        #pragma unroll
        for (int i = 1; i < 8; i++) m = fmaxf(m, red[i]);
        smax = m;
    }
    __syncthreads();
    const float mx = smax;

    // ---- row sums ----
    for (int i = wid; i < l1; i += 8) {
        const float ti = t1[i+1];
        float s = 0.f;
        #pragma unroll
        for (int base = 0; base < L_; base += 32) {
            int j = base + lane;
            if (j < l2) {
                float we = ti - t2[j+1];
                float m = (fabsf(we) < 1e-7f) ? -1e7f : we;
                s += __expf(m - mx);
            }
        }
        #pragma unroll
        for (int o = 16; o; o >>= 1) s += __shfl_xor_sync(0xffffffffu, s, o);
        if (lane == 0) rowsh[i] = s;
    }
    // ---- col sums ----
    for (int j = wid; j < l2; j += 8) {
        const float tj = t2[j+1];
        float s = 0.f;
        #pragma unroll
        for (int base = 0; base < L_; base += 32) {
            int i = base + lane;
            if (i < l1) {
                float we = t1[i+1] - tj;
                float m = (fabsf(we) < 1e-7f) ? -1e7f : we;
                s += __expf(m - mx);
            }
        }
        #pragma unroll
        for (int o = 16; o; o >>= 1) s += __shfl_xor_sync(0xffffffffu, s, o);
        if (lane == 0) colsh[j] = s;
    }
    __syncthreads();

    // ---- denom + coefficients in smem ----
    if (wid == 0) {
        float s = rowsh[lane] + rowsh[lane + 32];
        #pragma unroll
        for (int o = 16; o; o >>= 1) s += __shfl_xor_sync(0xffffffffu, s, o);
        if (lane == 0) {
            float pad = (float)(LL_ - l1*l2) * __expf(-1e7f - mx);
            sinvd = 1.f / (s + pad);
        }
    }
    __syncthreads();
    const float invd = sinvd;

    if (tid < L_) {
        ca[tid] = (tid >= 1 && tid - 1 < l1) ? rowsh[tid-1] * invd : 0.f;
    } else if (tid < 2*L_) {
        int j = tid - L_;
        cb[j] = (j >= 1 && j - 1 < l2) ? -colsh[j-1] * invd : 0.f;
    }
    __syncthreads();

    // ---- pooled chunk: columns [cc*32, cc*32+32) ----
    const int col = cc*32 + lane;
    const float4* base1v = (const float4*)(a1 + (size_t)b * L_ * D_);
    const float4* base2v = (const float4*)(a2 + (size_t)b * L_ * D_);

    float4 acc = make_float4(0.f, 0.f, 0.f, 0.f);
    #pragma unroll
    for (int k = 0; k < 8; k++) {
        const int r = wid + 8*k;           // 8 warps x 8 = 64 rows
        const float c1 = ca[r];
        const float c2 = cb[r];
        float4 v1 = base1v[r*(D_/4) + col];
        float4 v2 = base2v[r*(D_/4) + col];
        acc.x += c1*v1.x + c2*v2.x;
        acc.y += c1*v1.y + c2*v2.y;
        acc.z += c1*v1.z + c2*v2.z;
        acc.w += c1*v1.w + c2*v2.w;
    }
    partt[wid][lane] = acc;
    __syncthreads();

    if (tid < 32) {
        float4 s = partt[0][lane];
        #pragma unroll
        for (int k = 1; k < 8; k++) {
            float4 v = partt[k][lane];
            s.x += v.x; s.y += v.y; s.z += v.z; s.w += v.w;
        }
        ((float4*)g_pooled)[b*(D_/4) + col] = s;
    }
}

// ---------------------------------------------------------------------------
// B: out[b,o] = tanh( dot(pooled[b], fc_w[o]) + fc_b[o] )
// grid = 192, block = 512 (16 warps). ONE 8-row tile per block, no loop.
// Warp owns 2 batches; pooled hoisted into 12 float4 regs.
// ---------------------------------------------------------------------------
__global__ __launch_bounds__(512) void stageB(
    const float* __restrict__ fc_w, const float* __restrict__ fc_b,
    float* __restrict__ out)
{
    __shared__ float sB[8 * D_];   // 24 KB

    const int tid  = threadIdx.x;
    const int lane = tid & 31;
    const int wid  = tid >> 5;
    const int o0   = blockIdx.x * 8;
    const int b0   = wid * 2;      // 16 warps x 2 = 32 batches

    // stage 8x768 = 1536 float4, 3 per thread, independent
    {
        const float4* src = (const float4*)(fc_w + (size_t)o0 * D_);
        float4*       dst = (float4*)sB;
        #pragma unroll
        for (int k = 0; k < 3; k++)
            dst[tid + 512*k] = src[tid + 512*k];
    }

    // preload pooled for 2 batches (overlaps staging latency)
    const float4* poolv = (const float4*)g_pooled;
    float4 p[2][6];
    #pragma unroll
    for (int bb = 0; bb < 2; bb++)
        #pragma unroll
        for (int k = 0; k < 6; k++)
            p[bb][k] = poolv[(b0 + bb)*(D_/4) + lane + 32*k];

    __syncthreads();

    const float4* sBv = (const float4*)sB;
    #pragma unroll
    for (int r = 0; r < 8; r++) {
        const int o = o0 + r;
        float x0 = 0.f, x1 = 0.f;
        #pragma unroll
        for (int k = 0; k < 6; k++) {
            float4 w = sBv[r*(D_/4) + lane + 32*k];
            x0 += w.x*p[0][k].x + w.y*p[0][k].y + w.z*p[0][k].z + w.w*p[0][k].w;
            x1 += w.x*p[1][k].x + w.y*p[1][k].y + w.z*p[1][k].z + w.w*p[1][k].w;
        }
        #pragma unroll
        for (int off = 16; off; off >>= 1) {
            x0 += __shfl_xor_sync(0xffffffffu, x0, off);
            x1 += __shfl_xor_sync(0xffffffffu, x1, off);
        }
        if (lane == 0) {
            const float bias = fc_b[o];
            out[(size_t)(b0+0)*OUTD_ + o] = tanhf(x0 + bias);
            out[(size_t)(b0+1)*OUTD_ + o] = tanhf(x1 + bias);
        }
    }
}

extern "C" void kernel_launch(void* const* d_in, const int* in_sizes, int n_in,
                              void* d_out, int out_size)
{
    const float* a1   = (const float*)d_in[0];  // (B, L, D)
    const float* a2   = (const float*)d_in[1];  // (B, L, D)
    const int*   m1   = (const int*)  d_in[2];  // (B, L)
    const int*   m2   = (const int*)  d_in[3];  // (B, L)
    const float* we_w = (const float*)d_in[4];  // (1, D)
    const float* fc_w = (const float*)d_in[5];  // (2D, D)
    const float* fc_b = (const float*)d_in[6];  // (2D,)
    float* out = (float*)d_out;                 // (B, 2D)

    stageT<<<dim3(16, B_), 256>>>(a1, a2, we_w);
    stageMA2<<<dim3(6, B_), 256>>>(a1, a2, m1, m2);
    stageB<<<OUTD_/8, 512>>>(fc_w, fc_b, out);
}